// round 12
// baseline (speedup 1.0000x reference)
#include <cuda_runtime.h>

#define N_NODES  100000
#define N_EDGES  3200000
#define N_GRAPHS 1024
#define HID      64
#define NCLS     21
#define NBLK     391   // ceil(N_NODES / 256)

typedef unsigned long long ull;

// ---- scratch (zero-init at load; every replay restores zeros in final_kernel) ----
__device__ __align__(128) float2 g_degagg[N_NODES];   // (deg, sum_x) packed
__device__ __align__(128) int    g_cursor[N_NODES];
__device__ __align__(128) int    g_row [N_NODES];
__device__ __align__(128) int    g_alloc;             // CSR bump allocator
__device__ __align__(128) int    g_csr [N_EDGES];     // src ids grouped by dst
__device__ __align__(128) float2 g_nf  [N_NODES];     // (mean1, x) per node
__device__ __align__(128) float  g_pool[N_GRAPHS * HID];
__device__ __align__(128) float  g_gcnt[N_GRAPHS];

__device__ __forceinline__ int clamp_node(int i) {
    i = i < 0 ? 0 : i;
    return i >= N_NODES ? N_NODES - 1 : i;
}

// ---- packed fp32x2 helpers ----
__device__ __forceinline__ ull pk2(float lo, float hi) {
    ull d; asm("mov.b64 %0, {%1, %2};" : "=l"(d) : "f"(lo), "f"(hi)); return d;
}
__device__ __forceinline__ ull fma2(ull a, ull b, ull c) {
    ull d; asm("fma.rn.f32x2 %0, %1, %2, %3;" : "=l"(d) : "l"(a), "l"(b), "l"(c)); return d;
}
__device__ __forceinline__ float2 unpk2(ull v) {
    float lo, hi; asm("mov.b64 {%0, %1}, %2;" : "=f"(lo), "=f"(hi) : "l"(v));
    return make_float2(lo, hi);
}

// ---- #1 hist: packed (deg, agg1) via single red.v2 per edge + gcnt ----
__global__ void hist_kernel(const int* __restrict__ ei,
                            const int* __restrict__ batch,
                            const float* __restrict__ x) {
    int e = blockIdx.x * blockDim.x + threadIdx.x;
    if (e < N_NODES) {
        int b = batch[e];
        b = b < 0 ? 0 : (b >= N_GRAPHS ? N_GRAPHS - 1 : b);
        atomicAdd(&g_gcnt[b], 1.0f);
    }
    if (e >= N_EDGES) return;
    int s = clamp_node(ei[e]);
    int d = clamp_node(ei[N_EDGES + e]);
    float xv = x[s];
    asm volatile("red.global.add.v2.f32 [%0], {%1, %2};"
                 :: "l"(&g_degagg[d]), "f"(1.0f), "f"(xv) : "memory");
}

// ---- #2 scan: block-local scan + atomic bump allocation; emits nf ----
__global__ void scan_alloc_kernel(const float* __restrict__ x) {
    __shared__ int s[256];
    __shared__ int base;
    int t = threadIdx.x;
    int i = blockIdx.x * 256 + t;
    float2 da = (i < N_NODES) ? g_degagg[i] : make_float2(0.0f, 0.0f);
    int deg = (int)da.x;     // exact: counts << 2^24
    s[t] = deg;
    __syncthreads();
    for (int off = 1; off < 256; off <<= 1) {
        int tmp = 0;
        if (t >= off) tmp = s[t - off];
        __syncthreads();
        if (t >= off) s[t] += tmp;
        __syncthreads();
    }
    if (t == 255) base = atomicAdd(&g_alloc, s[255]);
    __syncthreads();
    if (i < N_NODES) {
        int r = base + s[t] - deg;
        g_row[i] = r;
        g_cursor[i] = r;
        g_nf[i] = make_float2(da.y / fmaxf(da.x, 1.0f), x[i]);
    }
}

// ---- #3 scatter: fill index CSR ----
__global__ void scatter_kernel(const int* __restrict__ ei) {
    int e = blockIdx.x * blockDim.x + threadIdx.x;
    if (e >= N_EDGES) return;
    int s = clamp_node(ei[e]);
    int d = clamp_node(ei[N_EDGES + e]);
    int pos = atomicAdd(&g_cursor[d], 1);
    g_csr[pos] = s;
}

// ==== #4 fused: agg2 (CSR + on-the-fly h1) -> GEMM (8x4 tiles) -> relu -> pool ====
// 128 threads, 64-node tile. Phase B micro-tile 8 nodes x 4 feats per thread.
#define SASTR 68
__global__ __launch_bounds__(128) void h2pool_gemm(
        const int* __restrict__ batch,
        const float* __restrict__ W2l,
        const float* __restrict__ b2,
        const float* __restrict__ W2r,
        const float* __restrict__ W1l,
        const float* __restrict__ b1,
        const float* __restrict__ W1r) {
    __shared__ __align__(16) float sA[64 * SASTR];  // [k][node]
    __shared__ __align__(16) float sB[64 * SASTR];  // [k][feat]
    __shared__ int    sBatch[64];
    __shared__ float2 sNF[64];

    int t    = threadIdx.x;
    int lane = t & 31;
    int wid  = t >> 5;       // 4 warps
    int n0   = blockIdx.x * 64;
    int tx   = t & 15;       // feat group (4 feats)
    int ty   = t >> 4;       // node group (8 nodes), 0..7

    if (t < 64) {
        int n = n0 + t;
        int b = -1;
        float2 nf = make_float2(0.0f, 0.0f);
        if (n < N_NODES) {
            b = batch[n];
            b = b < 0 ? 0 : (b >= N_GRAPHS ? N_GRAPHS - 1 : b);
            nf = g_nf[n];
        }
        sBatch[t] = b;
        sNF[t] = nf;
    }

    // fill sB with W2l while phase A runs
#pragma unroll
    for (int i = 0; i < 32; i++) {
        int idx = t + i * 128;
        int f = idx & 63, k = idx >> 6;
        sB[k * SASTR + f] = W2l[k * HID + f];
    }

    // ---- Phase A: per-warp neighbor-mean of h1 (16 nodes per warp) ----
    {
        float wl0 = W1l[lane],      wr0 = W1r[lane],      bb0 = b1[lane];
        float wl1 = W1l[lane + 32], wr1 = W1r[lane + 32], bb1 = b1[lane + 32];
#pragma unroll 1
        for (int r = 0; r < 16; r++) {
            int nl = wid * 16 + r;
            int n  = n0 + nl;
            float acc0 = 0.0f, acc1 = 0.0f;
            float degf = 0.0f;
            if (n < N_NODES) {
                int start = g_row[n];
                float2 da = g_degagg[n];
                degf = da.x;
                int deg = (int)degf;
                int end = start + deg;
                if (deg > 0) {
                    int idx0 = start + lane;
                    int s0 = (idx0 < end) ? g_csr[idx0] : 0;
                    float2 vcur = g_nf[s0];
#pragma unroll 1
                    for (int j = start; j < end; j += 32) {
                        float2 vnext = make_float2(0.0f, 0.0f);
                        if (j + 32 < end) {
                            int idx2 = j + 32 + lane;
                            int s2 = (idx2 < end) ? g_csr[idx2] : 0;
                            vnext = g_nf[s2];
                        }
                        int m = end - j; if (m > 32) m = 32;   // warp-uniform
                        if (m == 32) {
#pragma unroll
                            for (int jj = 0; jj < 32; jj++) {
                                float a  = __shfl_sync(0xffffffffu, vcur.x, jj);
                                float xx = __shfl_sync(0xffffffffu, vcur.y, jj);
                                acc0 += fmaxf(fmaf(a, wl0, fmaf(xx, wr0, bb0)), 0.0f);
                                acc1 += fmaxf(fmaf(a, wl1, fmaf(xx, wr1, bb1)), 0.0f);
                            }
                        } else {
                            for (int jj = 0; jj < m; jj++) {
                                float a  = __shfl_sync(0xffffffffu, vcur.x, jj);
                                float xx = __shfl_sync(0xffffffffu, vcur.y, jj);
                                acc0 += fmaxf(fmaf(a, wl0, fmaf(xx, wr0, bb0)), 0.0f);
                                acc1 += fmaxf(fmaf(a, wl1, fmaf(xx, wr1, bb1)), 0.0f);
                            }
                        }
                        vcur = vnext;
                    }
                }
            }
            float inv = 1.0f / fmaxf(degf, 1.0f);
            sA[lane * SASTR + nl]        = acc0 * inv;
            sA[(lane + 32) * SASTR + nl] = acc1 * inv;
        }
    }
    __syncthreads();

    // ---- Phase B: GEMM, 2 K-chunks, 8x4 micro-tile, packed f32x2 FMA ----
    ull acc2[8][2] = {};
#pragma unroll
    for (int ch = 0; ch < 2; ch++) {
#pragma unroll
        for (int k = 0; k < 64; k++) {
            float4 alo = *(const float4*)&sA[k * SASTR + ty * 8];
            float4 ahi = *(const float4*)&sA[k * SASTR + ty * 8 + 4];
            ulonglong2 b = *(const ulonglong2*)&sB[k * SASTR + tx * 4];
            ull a0 = pk2(alo.x, alo.x), a1 = pk2(alo.y, alo.y);
            ull a2 = pk2(alo.z, alo.z), a3 = pk2(alo.w, alo.w);
            ull a4 = pk2(ahi.x, ahi.x), a5 = pk2(ahi.y, ahi.y);
            ull a6 = pk2(ahi.z, ahi.z), a7 = pk2(ahi.w, ahi.w);
            acc2[0][0] = fma2(a0, b.x, acc2[0][0]); acc2[0][1] = fma2(a0, b.y, acc2[0][1]);
            acc2[1][0] = fma2(a1, b.x, acc2[1][0]); acc2[1][1] = fma2(a1, b.y, acc2[1][1]);
            acc2[2][0] = fma2(a2, b.x, acc2[2][0]); acc2[2][1] = fma2(a2, b.y, acc2[2][1]);
            acc2[3][0] = fma2(a3, b.x, acc2[3][0]); acc2[3][1] = fma2(a3, b.y, acc2[3][1]);
            acc2[4][0] = fma2(a4, b.x, acc2[4][0]); acc2[4][1] = fma2(a4, b.y, acc2[4][1]);
            acc2[5][0] = fma2(a5, b.x, acc2[5][0]); acc2[5][1] = fma2(a5, b.y, acc2[5][1]);
            acc2[6][0] = fma2(a6, b.x, acc2[6][0]); acc2[6][1] = fma2(a6, b.y, acc2[6][1]);
            acc2[7][0] = fma2(a7, b.x, acc2[7][0]); acc2[7][1] = fma2(a7, b.y, acc2[7][1]);
        }
        __syncthreads();
        if (ch == 0) {
            // refill sA with on-the-fly h1, sB with W2r
#pragma unroll
            for (int i = 0; i < 32; i++) {
                int idx = t + i * 128;
                int f = idx & 63, n = idx >> 6;
                float2 nf = sNF[n];
                float v = fmaxf(fmaf(nf.x, W1l[f], fmaf(nf.y, W1r[f], b1[f])), 0.0f);
                if (n0 + n >= N_NODES) v = 0.0f;
                sA[f * SASTR + n] = v;
            }
#pragma unroll
            for (int i = 0; i < 32; i++) {
                int idx = t + i * 128;
                int f = idx & 63, k = idx >> 6;
                sB[k * SASTR + f] = W2r[k * HID + f];
            }
            __syncthreads();
        }
    }

    // ---- Phase C: bias + relu -> stage h2 into sA [node][feat], then pool ----
#pragma unroll
    for (int i = 0; i < 8; i++) {
        float2 p0 = unpk2(acc2[i][0]);
        float2 p1 = unpk2(acc2[i][1]);
        int nrow = (ty * 8 + i) * SASTR + tx * 4;
        sA[nrow + 0] = fmaxf(p0.x + b2[tx * 4 + 0], 0.0f);
        sA[nrow + 1] = fmaxf(p0.y + b2[tx * 4 + 1], 0.0f);
        sA[nrow + 2] = fmaxf(p1.x + b2[tx * 4 + 2], 0.0f);
        sA[nrow + 3] = fmaxf(p1.y + b2[tx * 4 + 3], 0.0f);
    }
    __syncthreads();

    {
        int f = t & 63;
        int g = t >> 6;          // 0..1, 32 nodes each
        int cur = -2;
        float racc = 0.0f;
#pragma unroll
        for (int i = 0; i < 32; i++) {
            int n = g * 32 + i;
            int b = sBatch[n];
            if (b != cur) {
                if (cur >= 0) atomicAdd(&g_pool[cur * HID + f], racc);
                racc = 0.0f;
                cur = b;
            }
            if (b >= 0) racc += sA[n * SASTR + f];
        }
        if (cur >= 0) atomicAdd(&g_pool[cur * HID + f], racc);
    }
}

// ---- #5 classifier + restore-zeros for next replay ----
__global__ void final_kernel(const float* __restrict__ Wc,
                             const float* __restrict__ bc,
                             float* __restrict__ out) {
    int g = blockIdx.x;
    int lt = threadIdx.x;     // 32 threads

    if (lt < NCLS) {
        float inv = 1.0f / fmaxf(g_gcnt[g], 1.0f);
        float acc = bc[lt];
#pragma unroll
        for (int k = 0; k < HID; k++) {
            acc += g_pool[g * HID + k] * inv * Wc[k * NCLS + lt];
        }
        out[g * NCLS + lt] = acc;
    }
    __syncwarp();

#pragma unroll
    for (int k = lt; k < HID; k += 32) g_pool[g * HID + k] = 0.0f;
    if (lt == 0) g_gcnt[g] = 0.0f;

    int tid = g * 32 + lt;
    int stride = N_GRAPHS * 32;
    for (int j = tid; j < N_NODES; j += stride) g_degagg[j] = make_float2(0.0f, 0.0f);
    if (tid == 0) g_alloc = 0;
}

extern "C" void kernel_launch(void* const* d_in, const int* in_sizes, int n_in,
                              void* d_out, int out_size) {
    const float* x    = (const float*)d_in[0];
    const int*   ei   = (const int*)d_in[1];
    const int*   bat  = (const int*)d_in[2];
    const float* W1l  = (const float*)d_in[3];
    const float* b1   = (const float*)d_in[4];
    const float* W1r  = (const float*)d_in[5];
    const float* W2l  = (const float*)d_in[6];
    const float* b2   = (const float*)d_in[7];
    const float* W2r  = (const float*)d_in[8];
    const float* Wc   = (const float*)d_in[9];
    const float* bc   = (const float*)d_in[10];
    float*       out  = (float*)d_out;

    (void)in_sizes; (void)n_in; (void)out_size;

    hist_kernel<<<(N_EDGES + 255) / 256, 256>>>(ei, bat, x);      // #1
    scan_alloc_kernel<<<NBLK, 256>>>(x);                           // #2
    scatter_kernel<<<(N_EDGES + 255) / 256, 256>>>(ei);            // #3
    h2pool_gemm<<<(N_NODES + 63) / 64, 128>>>(bat, W2l, b2, W2r,   // #4 (ncu target)
                                              W1l, b1, W1r);
    final_kernel<<<N_GRAPHS, 32>>>(Wc, bc, out);                   // #5
}

// round 13
// speedup vs baseline: 1.1341x; 1.1341x over previous
#include <cuda_runtime.h>

#define N_NODES  100000
#define N_EDGES  3200000
#define N_GRAPHS 1024
#define HID      64
#define NCLS     21
#define NBLK     391   // ceil(N_NODES / 256)

typedef unsigned long long ull;

// ---- scratch (zero-init at load; every replay restores zeros in final_kernel) ----
__device__ __align__(128) float2 g_degagg[N_NODES];   // (deg, sum_x) packed
__device__ __align__(128) int    g_cursor[N_NODES];
__device__ __align__(128) int    g_row [N_NODES];
__device__ __align__(128) int    g_alloc;             // CSR bump allocator
__device__ __align__(128) int    g_csr [N_EDGES];     // src ids grouped by dst
__device__ __align__(128) float2 g_nf  [N_NODES];     // (mean1, x) per node
__device__ __align__(128) float  g_pool[N_GRAPHS * HID];
__device__ __align__(128) float  g_gcnt[N_GRAPHS];

__device__ __forceinline__ int clamp_node(int i) {
    i = i < 0 ? 0 : i;
    return i >= N_NODES ? N_NODES - 1 : i;
}

// ---- packed fp32x2 helpers ----
__device__ __forceinline__ ull pk2(float lo, float hi) {
    ull d; asm("mov.b64 %0, {%1, %2};" : "=l"(d) : "f"(lo), "f"(hi)); return d;
}
__device__ __forceinline__ ull fma2(ull a, ull b, ull c) {
    ull d; asm("fma.rn.f32x2 %0, %1, %2, %3;" : "=l"(d) : "l"(a), "l"(b), "l"(c)); return d;
}
__device__ __forceinline__ float2 unpk2(ull v) {
    float lo, hi; asm("mov.b64 {%0, %1}, %2;" : "=f"(lo), "=f"(hi) : "l"(v));
    return make_float2(lo, hi);
}

// ---- #1 hist: packed (deg, agg1) via single red.v2 per edge + gcnt ----
__global__ void hist_kernel(const int* __restrict__ ei,
                            const int* __restrict__ batch,
                            const float* __restrict__ x) {
    int e = blockIdx.x * blockDim.x + threadIdx.x;
    if (e < N_NODES) {
        int b = batch[e];
        b = b < 0 ? 0 : (b >= N_GRAPHS ? N_GRAPHS - 1 : b);
        atomicAdd(&g_gcnt[b], 1.0f);
    }
    if (e >= N_EDGES) return;
    int s = clamp_node(ei[e]);
    int d = clamp_node(ei[N_EDGES + e]);
    float xv = x[s];
    asm volatile("red.global.add.v2.f32 [%0], {%1, %2};"
                 :: "l"(&g_degagg[d]), "f"(1.0f), "f"(xv) : "memory");
}

// ---- #2 scan: block-local scan + atomic bump allocation; emits nf ----
__global__ void scan_alloc_kernel(const float* __restrict__ x) {
    __shared__ int s[256];
    __shared__ int base;
    int t = threadIdx.x;
    int i = blockIdx.x * 256 + t;
    float2 da = (i < N_NODES) ? g_degagg[i] : make_float2(0.0f, 0.0f);
    int deg = (int)da.x;     // exact: counts << 2^24
    s[t] = deg;
    __syncthreads();
    for (int off = 1; off < 256; off <<= 1) {
        int tmp = 0;
        if (t >= off) tmp = s[t - off];
        __syncthreads();
        if (t >= off) s[t] += tmp;
        __syncthreads();
    }
    if (t == 255) base = atomicAdd(&g_alloc, s[255]);
    __syncthreads();
    if (i < N_NODES) {
        int r = base + s[t] - deg;
        g_row[i] = r;
        g_cursor[i] = r;
        g_nf[i] = make_float2(da.y / fmaxf(da.x, 1.0f), x[i]);
    }
}

// ---- #3 scatter: fill index CSR ----
__global__ void scatter_kernel(const int* __restrict__ ei) {
    int e = blockIdx.x * blockDim.x + threadIdx.x;
    if (e >= N_EDGES) return;
    int s = clamp_node(ei[e]);
    int d = clamp_node(ei[N_EDGES + e]);
    int pos = atomicAdd(&g_cursor[d], 1);
    g_csr[pos] = s;
}

// ==== #4 fused: agg2 (CSR + on-the-fly h1) -> GEMM -> relu -> pool ====
// R11 configuration: 256 threads, 64-node tile, 4x4 micro-tile, 8 nodes/warp phase A.
#define SASTR 68
__global__ __launch_bounds__(256) void h2pool_gemm(
        const int* __restrict__ batch,
        const float* __restrict__ W2l,
        const float* __restrict__ b2,
        const float* __restrict__ W2r,
        const float* __restrict__ W1l,
        const float* __restrict__ b1,
        const float* __restrict__ W1r) {
    __shared__ __align__(16) float sA[64 * SASTR];  // [k][node]
    __shared__ __align__(16) float sB[64 * SASTR];  // [k][feat]
    __shared__ int    sBatch[64];
    __shared__ float2 sNF[64];

    int t    = threadIdx.x;
    int lane = t & 31;
    int wid  = t >> 5;       // 8 warps
    int n0   = blockIdx.x * 64;
    int tx   = t & 15;
    int ty   = t >> 4;

    if (t < 64) {
        int n = n0 + t;
        int b = -1;
        float2 nf = make_float2(0.0f, 0.0f);
        if (n < N_NODES) {
            b = batch[n];
            b = b < 0 ? 0 : (b >= N_GRAPHS ? N_GRAPHS - 1 : b);
            nf = g_nf[n];
        }
        sBatch[t] = b;
        sNF[t] = nf;
    }

    // fill sB with W2l while phase A runs
#pragma unroll
    for (int i = 0; i < 16; i++) {
        int idx = t + i * 256;
        int f = idx & 63, k = idx >> 6;
        sB[k * SASTR + f] = W2l[k * HID + f];
    }

    // ---- Phase A: per-warp neighbor-mean of h1 (8 nodes/warp, prefetch) ----
    {
        float wl0 = W1l[lane],      wr0 = W1r[lane],      bb0 = b1[lane];
        float wl1 = W1l[lane + 32], wr1 = W1r[lane + 32], bb1 = b1[lane + 32];
#pragma unroll 1
        for (int r = 0; r < 8; r++) {
            int nl = wid * 8 + r;
            int n  = n0 + nl;
            float acc0 = 0.0f, acc1 = 0.0f;
            float degf = 0.0f;
            if (n < N_NODES) {
                int start = g_row[n];
                float2 da = g_degagg[n];
                degf = da.x;
                int deg = (int)degf;
                int end = start + deg;
                if (deg > 0) {
                    int idx0 = start + lane;
                    int s0 = (idx0 < end) ? g_csr[idx0] : 0;
                    float2 vcur = g_nf[s0];
#pragma unroll 1
                    for (int j = start; j < end; j += 32) {
                        float2 vnext = make_float2(0.0f, 0.0f);
                        if (j + 32 < end) {
                            int idx2 = j + 32 + lane;
                            int s2 = (idx2 < end) ? g_csr[idx2] : 0;
                            vnext = g_nf[s2];
                        }
                        int m = end - j; if (m > 32) m = 32;   // warp-uniform
                        if (m == 32) {
#pragma unroll
                            for (int jj = 0; jj < 32; jj++) {
                                float a  = __shfl_sync(0xffffffffu, vcur.x, jj);
                                float xx = __shfl_sync(0xffffffffu, vcur.y, jj);
                                acc0 += fmaxf(fmaf(a, wl0, fmaf(xx, wr0, bb0)), 0.0f);
                                acc1 += fmaxf(fmaf(a, wl1, fmaf(xx, wr1, bb1)), 0.0f);
                            }
                        } else {
                            for (int jj = 0; jj < m; jj++) {
                                float a  = __shfl_sync(0xffffffffu, vcur.x, jj);
                                float xx = __shfl_sync(0xffffffffu, vcur.y, jj);
                                acc0 += fmaxf(fmaf(a, wl0, fmaf(xx, wr0, bb0)), 0.0f);
                                acc1 += fmaxf(fmaf(a, wl1, fmaf(xx, wr1, bb1)), 0.0f);
                            }
                        }
                        vcur = vnext;
                    }
                }
            }
            float inv = 1.0f / fmaxf(degf, 1.0f);
            sA[lane * SASTR + nl]        = acc0 * inv;
            sA[(lane + 32) * SASTR + nl] = acc1 * inv;
        }
    }
    __syncthreads();

    // ---- Phase B: GEMM, 2 K-chunks, 4x4 micro-tile, packed f32x2 FMA ----
    ull acc2[4][2] = {};
#pragma unroll
    for (int ch = 0; ch < 2; ch++) {
#pragma unroll
        for (int k = 0; k < 64; k++) {
            float4 a = *(const float4*)&sA[k * SASTR + ty * 4];
            ulonglong2 b = *(const ulonglong2*)&sB[k * SASTR + tx * 4];
            ull a0 = pk2(a.x, a.x), a1 = pk2(a.y, a.y);
            ull a2 = pk2(a.z, a.z), a3 = pk2(a.w, a.w);
            acc2[0][0] = fma2(a0, b.x, acc2[0][0]); acc2[0][1] = fma2(a0, b.y, acc2[0][1]);
            acc2[1][0] = fma2(a1, b.x, acc2[1][0]); acc2[1][1] = fma2(a1, b.y, acc2[1][1]);
            acc2[2][0] = fma2(a2, b.x, acc2[2][0]); acc2[2][1] = fma2(a2, b.y, acc2[2][1]);
            acc2[3][0] = fma2(a3, b.x, acc2[3][0]); acc2[3][1] = fma2(a3, b.y, acc2[3][1]);
        }
        __syncthreads();
        if (ch == 0) {
            // refill sA with on-the-fly h1, sB with W2r
#pragma unroll
            for (int i = 0; i < 16; i++) {
                int idx = t + i * 256;
                int f = idx & 63, n = idx >> 6;
                float2 nf = sNF[n];
                float v = fmaxf(fmaf(nf.x, W1l[f], fmaf(nf.y, W1r[f], b1[f])), 0.0f);
                if (n0 + n >= N_NODES) v = 0.0f;
                sA[f * SASTR + n] = v;
            }
#pragma unroll
            for (int i = 0; i < 16; i++) {
                int idx = t + i * 256;
                int f = idx & 63, k = idx >> 6;
                sB[k * SASTR + f] = W2r[k * HID + f];
            }
            __syncthreads();
        }
    }

    // ---- Phase C: bias + relu -> stage h2 into sA [node][feat], then pool ----
#pragma unroll
    for (int i = 0; i < 4; i++) {
        float2 p0 = unpk2(acc2[i][0]);
        float2 p1 = unpk2(acc2[i][1]);
        int nrow = (ty * 4 + i) * SASTR + tx * 4;
        sA[nrow + 0] = fmaxf(p0.x + b2[tx * 4 + 0], 0.0f);
        sA[nrow + 1] = fmaxf(p0.y + b2[tx * 4 + 1], 0.0f);
        sA[nrow + 2] = fmaxf(p1.x + b2[tx * 4 + 2], 0.0f);
        sA[nrow + 3] = fmaxf(p1.y + b2[tx * 4 + 3], 0.0f);
    }
    __syncthreads();

    {
        int f = t & 63;
        int g = t >> 6;
        int cur = -2;
        float racc = 0.0f;
#pragma unroll
        for (int i = 0; i < 16; i++) {
            int n = g * 16 + i;
            int b = sBatch[n];
            if (b != cur) {
                if (cur >= 0) atomicAdd(&g_pool[cur * HID + f], racc);
                racc = 0.0f;
                cur = b;
            }
            if (b >= 0) racc += sA[n * SASTR + f];
        }
        if (cur >= 0) atomicAdd(&g_pool[cur * HID + f], racc);
    }
}

// ---- #5 classifier + restore-zeros for next replay ----
__global__ void final_kernel(const float* __restrict__ Wc,
                             const float* __restrict__ bc,
                             float* __restrict__ out) {
    int g = blockIdx.x;
    int lt = threadIdx.x;     // 32 threads

    if (lt < NCLS) {
        float inv = 1.0f / fmaxf(g_gcnt[g], 1.0f);
        float acc = bc[lt];
#pragma unroll
        for (int k = 0; k < HID; k++) {
            acc += g_pool[g * HID + k] * inv * Wc[k * NCLS + lt];
        }
        out[g * NCLS + lt] = acc;
    }
    __syncwarp();

#pragma unroll
    for (int k = lt; k < HID; k += 32) g_pool[g * HID + k] = 0.0f;
    if (lt == 0) g_gcnt[g] = 0.0f;

    int tid = g * 32 + lt;
    int stride = N_GRAPHS * 32;
    for (int j = tid; j < N_NODES; j += stride) g_degagg[j] = make_float2(0.0f, 0.0f);
    if (tid == 0) g_alloc = 0;
}

extern "C" void kernel_launch(void* const* d_in, const int* in_sizes, int n_in,
                              void* d_out, int out_size) {
    const float* x    = (const float*)d_in[0];
    const int*   ei   = (const int*)d_in[1];
    const int*   bat  = (const int*)d_in[2];
    const float* W1l  = (const float*)d_in[3];
    const float* b1   = (const float*)d_in[4];
    const float* W1r  = (const float*)d_in[5];
    const float* W2l  = (const float*)d_in[6];
    const float* b2   = (const float*)d_in[7];
    const float* W2r  = (const float*)d_in[8];
    const float* Wc   = (const float*)d_in[9];
    const float* bc   = (const float*)d_in[10];
    float*       out  = (float*)d_out;

    (void)in_sizes; (void)n_in; (void)out_size;

    hist_kernel<<<(N_EDGES + 255) / 256, 256>>>(ei, bat, x);      // #1
    scan_alloc_kernel<<<NBLK, 256>>>(x);                           // #2
    scatter_kernel<<<(N_EDGES + 255) / 256, 256>>>(ei);            // #3
    h2pool_gemm<<<(N_NODES + 63) / 64, 256>>>(bat, W2l, b2, W2r,   // #4 (ncu target)
                                              W1l, b1, W1r);
    final_kernel<<<N_GRAPHS, 32>>>(Wc, bc, out);                   // #5
}

// round 14
// speedup vs baseline: 1.1626x; 1.0251x over previous
#include <cuda_runtime.h>

#define N_NODES  100000
#define N_EDGES  3200000
#define N_GRAPHS 1024
#define HID      64
#define NCLS     21
#define NBLK     391   // ceil(N_NODES / 256)

typedef unsigned long long ull;

// ---- scratch (zero-init at load; every replay restores zeros in final_kernel) ----
__device__ __align__(128) float2 g_degagg[N_NODES];   // (deg, sum_x) packed
__device__ __align__(128) int    g_cursor[N_NODES];
__device__ __align__(128) int    g_row [N_NODES];
__device__ __align__(128) int    g_alloc;             // CSR bump allocator
__device__ __align__(128) int    g_csr [N_EDGES];     // src ids grouped by dst
__device__ __align__(128) float2 g_nf  [N_NODES];     // (mean1, x) per node
__device__ __align__(128) float  g_pool[N_GRAPHS * HID];
__device__ __align__(128) float  g_gcnt[N_GRAPHS];

__device__ __forceinline__ int clamp_node(int i) {
    i = i < 0 ? 0 : i;
    return i >= N_NODES ? N_NODES - 1 : i;
}

// ---- packed fp32x2 helpers ----
__device__ __forceinline__ ull pk2(float lo, float hi) {
    ull d; asm("mov.b64 %0, {%1, %2};" : "=l"(d) : "f"(lo), "f"(hi)); return d;
}
__device__ __forceinline__ ull fma2(ull a, ull b, ull c) {
    ull d; asm("fma.rn.f32x2 %0, %1, %2, %3;" : "=l"(d) : "l"(a), "l"(b), "l"(c)); return d;
}
__device__ __forceinline__ float2 unpk2(ull v) {
    float lo, hi; asm("mov.b64 {%0, %1}, %2;" : "=f"(lo), "=f"(hi) : "l"(v));
    return make_float2(lo, hi);
}

// ---- #1 hist: packed (deg, agg1) via single red.v2 per edge + gcnt ----
__global__ void hist_kernel(const int* __restrict__ ei,
                            const int* __restrict__ batch,
                            const float* __restrict__ x) {
    int e = blockIdx.x * blockDim.x + threadIdx.x;
    if (e < N_NODES) {
        int b = batch[e];
        b = b < 0 ? 0 : (b >= N_GRAPHS ? N_GRAPHS - 1 : b);
        atomicAdd(&g_gcnt[b], 1.0f);
    }
    if (e >= N_EDGES) return;
    int s = clamp_node(ei[e]);
    int d = clamp_node(ei[N_EDGES + e]);
    float xv = x[s];
    asm volatile("red.global.add.v2.f32 [%0], {%1, %2};"
                 :: "l"(&g_degagg[d]), "f"(1.0f), "f"(xv) : "memory");
}

// ---- #2 scan: block-local scan + atomic bump allocation; emits nf ----
__global__ void scan_alloc_kernel(const float* __restrict__ x) {
    __shared__ int s[256];
    __shared__ int base;
    int t = threadIdx.x;
    int i = blockIdx.x * 256 + t;
    float2 da = (i < N_NODES) ? g_degagg[i] : make_float2(0.0f, 0.0f);
    int deg = (int)da.x;     // exact: counts << 2^24
    s[t] = deg;
    __syncthreads();
    for (int off = 1; off < 256; off <<= 1) {
        int tmp = 0;
        if (t >= off) tmp = s[t - off];
        __syncthreads();
        if (t >= off) s[t] += tmp;
        __syncthreads();
    }
    if (t == 255) base = atomicAdd(&g_alloc, s[255]);
    __syncthreads();
    if (i < N_NODES) {
        int r = base + s[t] - deg;
        g_row[i] = r;
        g_cursor[i] = r;
        g_nf[i] = make_float2(da.y / fmaxf(da.x, 1.0f), x[i]);
    }
}

// ---- #3 scatter: fill index CSR ----
__global__ void scatter_kernel(const int* __restrict__ ei) {
    int e = blockIdx.x * blockDim.x + threadIdx.x;
    if (e >= N_EDGES) return;
    int s = clamp_node(ei[e]);
    int d = clamp_node(ei[N_EDGES + e]);
    int pos = atomicAdd(&g_cursor[d], 1);
    g_csr[pos] = s;
}

// ---- phase A inner compute: accumulate m neighbors' h1 into (acc0, acc1) ----
__device__ __forceinline__ void accum_chunk(
        float2 v, int m, float& acc0, float& acc1,
        float wl0, float wr0, float bb0,
        float wl1, float wr1, float bb1) {
    if (m == 32) {
#pragma unroll
        for (int jj = 0; jj < 32; jj++) {
            float a  = __shfl_sync(0xffffffffu, v.x, jj);
            float xx = __shfl_sync(0xffffffffu, v.y, jj);
            acc0 += fmaxf(fmaf(a, wl0, fmaf(xx, wr0, bb0)), 0.0f);
            acc1 += fmaxf(fmaf(a, wl1, fmaf(xx, wr1, bb1)), 0.0f);
        }
    } else {
        for (int jj = 0; jj < m; jj++) {
            float a  = __shfl_sync(0xffffffffu, v.x, jj);
            float xx = __shfl_sync(0xffffffffu, v.y, jj);
            acc0 += fmaxf(fmaf(a, wl0, fmaf(xx, wr0, bb0)), 0.0f);
            acc1 += fmaxf(fmaf(a, wl1, fmaf(xx, wr1, bb1)), 0.0f);
        }
    }
}

// ==== #4 fused: agg2 (CSR + on-the-fly h1) -> GEMM -> relu -> pool ====
// 256 threads, 64-node tile, 4x4 micro-tile; phase A processes node PAIRS
// per warp iteration (dual gather streams -> 2x MLP on the csr->nf chain).
#define SASTR 68
__global__ __launch_bounds__(256, 4) void h2pool_gemm(
        const int* __restrict__ batch,
        const float* __restrict__ W2l,
        const float* __restrict__ b2,
        const float* __restrict__ W2r,
        const float* __restrict__ W1l,
        const float* __restrict__ b1,
        const float* __restrict__ W1r) {
    __shared__ __align__(16) float sA[64 * SASTR];  // [k][node]
    __shared__ __align__(16) float sB[64 * SASTR];  // [k][feat]
    __shared__ int    sBatch[64];
    __shared__ float2 sNF[64];

    int t    = threadIdx.x;
    int lane = t & 31;
    int wid  = t >> 5;       // 8 warps
    int n0   = blockIdx.x * 64;
    int tx   = t & 15;
    int ty   = t >> 4;

    if (t < 64) {
        int n = n0 + t;
        int b = -1;
        float2 nf = make_float2(0.0f, 0.0f);
        if (n < N_NODES) {
            b = batch[n];
            b = b < 0 ? 0 : (b >= N_GRAPHS ? N_GRAPHS - 1 : b);
            nf = g_nf[n];
        }
        sBatch[t] = b;
        sNF[t] = nf;
    }

    // fill sB with W2l while phase A runs
#pragma unroll
    for (int i = 0; i < 16; i++) {
        int idx = t + i * 256;
        int f = idx & 63, k = idx >> 6;
        sB[k * SASTR + f] = W2l[k * HID + f];
    }

    // ---- Phase A: neighbor-mean of h1, 2 nodes in flight per warp ----
    {
        float wl0 = W1l[lane],      wr0 = W1r[lane],      bb0 = b1[lane];
        float wl1 = W1l[lane + 32], wr1 = W1r[lane + 32], bb1 = b1[lane + 32];
#pragma unroll 1
        for (int r = 0; r < 8; r += 2) {
            int nlA = wid * 8 + r;
            int nlB = nlA + 1;
            int nA = n0 + nlA, nB = n0 + nlB;
            float accA0 = 0.0f, accA1 = 0.0f, accB0 = 0.0f, accB1 = 0.0f;
            float degA = 0.0f, degB = 0.0f;
            int jA = 0, eA = 0, jB = 0, eB = 0;
            if (nA < N_NODES) {
                jA = g_row[nA];
                float2 da = g_degagg[nA];
                degA = da.x;
                eA = jA + (int)degA;
            }
            if (nB < N_NODES) {
                jB = g_row[nB];
                float2 db = g_degagg[nB];
                degB = db.x;
                eB = jB + (int)degB;
            }
#pragma unroll 1
            while (jA < eA || jB < eB) {
                int mA = 0, mB = 0;
                float2 vA = make_float2(0.0f, 0.0f);
                float2 vB = make_float2(0.0f, 0.0f);
                // issue BOTH gather chains before any compute
                if (jA < eA) {
                    int idx = jA + lane;
                    int s = (idx < eA) ? g_csr[idx] : 0;
                    vA = g_nf[s];
                    mA = eA - jA; if (mA > 32) mA = 32;
                }
                if (jB < eB) {
                    int idx = jB + lane;
                    int s = (idx < eB) ? g_csr[idx] : 0;
                    vB = g_nf[s];
                    mB = eB - jB; if (mB > 32) mB = 32;
                }
                if (mA) accum_chunk(vA, mA, accA0, accA1, wl0, wr0, bb0, wl1, wr1, bb1);
                if (mB) accum_chunk(vB, mB, accB0, accB1, wl0, wr0, bb0, wl1, wr1, bb1);
                jA += 32;
                jB += 32;
            }
            float invA = 1.0f / fmaxf(degA, 1.0f);
            float invB = 1.0f / fmaxf(degB, 1.0f);
            sA[lane * SASTR + nlA]        = accA0 * invA;
            sA[(lane + 32) * SASTR + nlA] = accA1 * invA;
            sA[lane * SASTR + nlB]        = accB0 * invB;
            sA[(lane + 32) * SASTR + nlB] = accB1 * invB;
        }
    }
    __syncthreads();

    // ---- Phase B: GEMM, 2 K-chunks, 4x4 micro-tile, packed f32x2 FMA ----
    ull acc2[4][2] = {};
#pragma unroll
    for (int ch = 0; ch < 2; ch++) {
#pragma unroll
        for (int k = 0; k < 64; k++) {
            float4 a = *(const float4*)&sA[k * SASTR + ty * 4];
            ulonglong2 b = *(const ulonglong2*)&sB[k * SASTR + tx * 4];
            ull a0 = pk2(a.x, a.x), a1 = pk2(a.y, a.y);
            ull a2 = pk2(a.z, a.z), a3 = pk2(a.w, a.w);
            acc2[0][0] = fma2(a0, b.x, acc2[0][0]); acc2[0][1] = fma2(a0, b.y, acc2[0][1]);
            acc2[1][0] = fma2(a1, b.x, acc2[1][0]); acc2[1][1] = fma2(a1, b.y, acc2[1][1]);
            acc2[2][0] = fma2(a2, b.x, acc2[2][0]); acc2[2][1] = fma2(a2, b.y, acc2[2][1]);
            acc2[3][0] = fma2(a3, b.x, acc2[3][0]); acc2[3][1] = fma2(a3, b.y, acc2[3][1]);
        }
        __syncthreads();
        if (ch == 0) {
            // refill sA with on-the-fly h1, sB with W2r
#pragma unroll
            for (int i = 0; i < 16; i++) {
                int idx = t + i * 256;
                int f = idx & 63, n = idx >> 6;
                float2 nf = sNF[n];
                float v = fmaxf(fmaf(nf.x, W1l[f], fmaf(nf.y, W1r[f], b1[f])), 0.0f);
                if (n0 + n >= N_NODES) v = 0.0f;
                sA[f * SASTR + n] = v;
            }
#pragma unroll
            for (int i = 0; i < 16; i++) {
                int idx = t + i * 256;
                int f = idx & 63, k = idx >> 6;
                sB[k * SASTR + f] = W2r[k * HID + f];
            }
            __syncthreads();
        }
    }

    // ---- Phase C: bias + relu -> stage h2 into sA [node][feat], then pool ----
#pragma unroll
    for (int i = 0; i < 4; i++) {
        float2 p0 = unpk2(acc2[i][0]);
        float2 p1 = unpk2(acc2[i][1]);
        int nrow = (ty * 4 + i) * SASTR + tx * 4;
        sA[nrow + 0] = fmaxf(p0.x + b2[tx * 4 + 0], 0.0f);
        sA[nrow + 1] = fmaxf(p0.y + b2[tx * 4 + 1], 0.0f);
        sA[nrow + 2] = fmaxf(p1.x + b2[tx * 4 + 2], 0.0f);
        sA[nrow + 3] = fmaxf(p1.y + b2[tx * 4 + 3], 0.0f);
    }
    __syncthreads();

    {
        int f = t & 63;
        int g = t >> 6;
        int cur = -2;
        float racc = 0.0f;
#pragma unroll
        for (int i = 0; i < 16; i++) {
            int n = g * 16 + i;
            int b = sBatch[n];
            if (b != cur) {
                if (cur >= 0) atomicAdd(&g_pool[cur * HID + f], racc);
                racc = 0.0f;
                cur = b;
            }
            if (b >= 0) racc += sA[n * SASTR + f];
        }
        if (cur >= 0) atomicAdd(&g_pool[cur * HID + f], racc);
    }
}

// ---- #5 classifier + restore-zeros for next replay ----
__global__ void final_kernel(const float* __restrict__ Wc,
                             const float* __restrict__ bc,
                             float* __restrict__ out) {
    int g = blockIdx.x;
    int lt = threadIdx.x;     // 32 threads

    if (lt < NCLS) {
        float inv = 1.0f / fmaxf(g_gcnt[g], 1.0f);
        float acc = bc[lt];
#pragma unroll
        for (int k = 0; k < HID; k++) {
            acc += g_pool[g * HID + k] * inv * Wc[k * NCLS + lt];
        }
        out[g * NCLS + lt] = acc;
    }
    __syncwarp();

#pragma unroll
    for (int k = lt; k < HID; k += 32) g_pool[g * HID + k] = 0.0f;
    if (lt == 0) g_gcnt[g] = 0.0f;

    int tid = g * 32 + lt;
    int stride = N_GRAPHS * 32;
    for (int j = tid; j < N_NODES; j += stride) g_degagg[j] = make_float2(0.0f, 0.0f);
    if (tid == 0) g_alloc = 0;
}

extern "C" void kernel_launch(void* const* d_in, const int* in_sizes, int n_in,
                              void* d_out, int out_size) {
    const float* x    = (const float*)d_in[0];
    const int*   ei   = (const int*)d_in[1];
    const int*   bat  = (const int*)d_in[2];
    const float* W1l  = (const float*)d_in[3];
    const float* b1   = (const float*)d_in[4];
    const float* W1r  = (const float*)d_in[5];
    const float* W2l  = (const float*)d_in[6];
    const float* b2   = (const float*)d_in[7];
    const float* W2r  = (const float*)d_in[8];
    const float* Wc   = (const float*)d_in[9];
    const float* bc   = (const float*)d_in[10];
    float*       out  = (float*)d_out;

    (void)in_sizes; (void)n_in; (void)out_size;

    hist_kernel<<<(N_EDGES + 255) / 256, 256>>>(ei, bat, x);      // #1
    scan_alloc_kernel<<<NBLK, 256>>>(x);                           // #2
    scatter_kernel<<<(N_EDGES + 255) / 256, 256>>>(ei);            // #3
    h2pool_gemm<<<(N_NODES + 63) / 64, 256>>>(bat, W2l, b2, W2r,   // #4 (ncu target)
                                              W1l, b1, W1r);
    final_kernel<<<N_GRAPHS, 32>>>(Wc, bc, out);                   // #5
}

// round 15
// speedup vs baseline: 1.2349x; 1.0621x over previous
#include <cuda_runtime.h>

#define N_NODES  100000
#define N_EDGES  3200000
#define N_GRAPHS 1024
#define HID      64
#define NCLS     21
#define ELL_LOG  7
#define ELL_STR  128          // slots per node; P(deg>128) ~ 1e-40 for Poisson(32)

typedef unsigned long long ull;

// ---- scratch (zero-init at load; every replay restores zeros in final_kernel) ----
__device__ __align__(128) int    g_cursor[N_NODES];            // per-node slot counter == degree
__device__ __align__(128) float  g_agg1[N_NODES];              // sum of neighbor x
__device__ __align__(128) int    g_csr [N_NODES * ELL_STR];    // ELL: src ids, row n at n<<7
__device__ __align__(128) float2 g_nf  [N_NODES];              // (mean1, x) per node
__device__ __align__(128) float  g_pool[N_GRAPHS * HID];
__device__ __align__(128) float  g_gcnt[N_GRAPHS];

__device__ __forceinline__ int clamp_node(int i) {
    i = i < 0 ? 0 : i;
    return i >= N_NODES ? N_NODES - 1 : i;
}

// ---- packed fp32x2 helpers ----
__device__ __forceinline__ ull pk2(float lo, float hi) {
    ull d; asm("mov.b64 %0, {%1, %2};" : "=l"(d) : "f"(lo), "f"(hi)); return d;
}
__device__ __forceinline__ ull fma2(ull a, ull b, ull c) {
    ull d; asm("fma.rn.f32x2 %0, %1, %2, %3;" : "=l"(d) : "l"(a), "l"(b), "l"(c)); return d;
}
__device__ __forceinline__ float2 unpk2(ull v) {
    float lo, hi; asm("mov.b64 {%0, %1}, %2;" : "=f"(lo), "=f"(hi) : "l"(v));
    return make_float2(lo, hi);
}

// ---- #1 ell: single edge pass -> ELL fill + degree + agg1 + graph counts ----
__global__ void ell_kernel(const int* __restrict__ ei,
                           const int* __restrict__ batch,
                           const float* __restrict__ x) {
    int e = blockIdx.x * blockDim.x + threadIdx.x;
    if (e < N_NODES) {
        int b = batch[e];
        b = b < 0 ? 0 : (b >= N_GRAPHS ? N_GRAPHS - 1 : b);
        atomicAdd(&g_gcnt[b], 1.0f);
    }
    if (e >= N_EDGES) return;
    int s = clamp_node(ei[e]);
    int d = clamp_node(ei[N_EDGES + e]);
    int c = atomicAdd(&g_cursor[d], 1);
    if (c > ELL_STR - 1) c = ELL_STR - 1;      // statistically unreachable
    g_csr[(d << ELL_LOG) + c] = s;
    atomicAdd(&g_agg1[d], x[s]);
}

// ---- #2 nf: elementwise (mean1, x) ----
__global__ void nf_kernel(const float* __restrict__ x) {
    int n = blockIdx.x * blockDim.x + threadIdx.x;
    if (n >= N_NODES) return;
    float deg = (float)g_cursor[n];
    g_nf[n] = make_float2(g_agg1[n] / fmaxf(deg, 1.0f), x[n]);
}

// ---- phase A inner compute: accumulate m neighbors' h1 into (acc0, acc1) ----
__device__ __forceinline__ void accum_chunk(
        float2 v, int m, float& acc0, float& acc1,
        float wl0, float wr0, float bb0,
        float wl1, float wr1, float bb1) {
    if (m == 32) {
#pragma unroll
        for (int jj = 0; jj < 32; jj++) {
            float a  = __shfl_sync(0xffffffffu, v.x, jj);
            float xx = __shfl_sync(0xffffffffu, v.y, jj);
            acc0 += fmaxf(fmaf(a, wl0, fmaf(xx, wr0, bb0)), 0.0f);
            acc1 += fmaxf(fmaf(a, wl1, fmaf(xx, wr1, bb1)), 0.0f);
        }
    } else {
        for (int jj = 0; jj < m; jj++) {
            float a  = __shfl_sync(0xffffffffu, v.x, jj);
            float xx = __shfl_sync(0xffffffffu, v.y, jj);
            acc0 += fmaxf(fmaf(a, wl0, fmaf(xx, wr0, bb0)), 0.0f);
            acc1 += fmaxf(fmaf(a, wl1, fmaf(xx, wr1, bb1)), 0.0f);
        }
    }
}

// ==== #3 fused: agg2 (ELL + on-the-fly h1) -> GEMM -> relu -> pool ====
// 256 threads, 64-node tile, 4x4 micro-tile; phase A: 2 nodes in flight/warp.
#define SASTR 68
__global__ __launch_bounds__(256, 4) void h2pool_gemm(
        const int* __restrict__ batch,
        const float* __restrict__ W2l,
        const float* __restrict__ b2,
        const float* __restrict__ W2r,
        const float* __restrict__ W1l,
        const float* __restrict__ b1,
        const float* __restrict__ W1r) {
    __shared__ __align__(16) float sA[64 * SASTR];  // [k][node]
    __shared__ __align__(16) float sB[64 * SASTR];  // [k][feat]
    __shared__ int    sBatch[64];
    __shared__ float2 sNF[64];

    int t    = threadIdx.x;
    int lane = t & 31;
    int wid  = t >> 5;       // 8 warps
    int n0   = blockIdx.x * 64;
    int tx   = t & 15;
    int ty   = t >> 4;

    if (t < 64) {
        int n = n0 + t;
        int b = -1;
        float2 nf = make_float2(0.0f, 0.0f);
        if (n < N_NODES) {
            b = batch[n];
            b = b < 0 ? 0 : (b >= N_GRAPHS ? N_GRAPHS - 1 : b);
            nf = g_nf[n];
        }
        sBatch[t] = b;
        sNF[t] = nf;
    }

    // fill sB with W2l while phase A runs
#pragma unroll
    for (int i = 0; i < 16; i++) {
        int idx = t + i * 256;
        int f = idx & 63, k = idx >> 6;
        sB[k * SASTR + f] = W2l[k * HID + f];
    }

    // ---- Phase A: neighbor-mean of h1, 2 nodes in flight per warp ----
    {
        float wl0 = W1l[lane],      wr0 = W1r[lane],      bb0 = b1[lane];
        float wl1 = W1l[lane + 32], wr1 = W1r[lane + 32], bb1 = b1[lane + 32];
#pragma unroll 1
        for (int r = 0; r < 8; r += 2) {
            int nlA = wid * 8 + r;
            int nlB = nlA + 1;
            int nA = n0 + nlA, nB = n0 + nlB;
            float accA0 = 0.0f, accA1 = 0.0f, accB0 = 0.0f, accB1 = 0.0f;
            float degA = 0.0f, degB = 0.0f;
            int jA = 0, eA = 0, jB = 0, eB = 0;
            if (nA < N_NODES) {
                int dg = g_cursor[nA];
                if (dg > ELL_STR) dg = ELL_STR;
                degA = (float)dg;
                jA = nA << ELL_LOG;
                eA = jA + dg;
            }
            if (nB < N_NODES) {
                int dg = g_cursor[nB];
                if (dg > ELL_STR) dg = ELL_STR;
                degB = (float)dg;
                jB = nB << ELL_LOG;
                eB = jB + dg;
            }
#pragma unroll 1
            while (jA < eA || jB < eB) {
                int mA = 0, mB = 0;
                float2 vA = make_float2(0.0f, 0.0f);
                float2 vB = make_float2(0.0f, 0.0f);
                if (jA < eA) {
                    int idx = jA + lane;
                    int s = (idx < eA) ? g_csr[idx] : 0;
                    vA = g_nf[s];
                    mA = eA - jA; if (mA > 32) mA = 32;
                }
                if (jB < eB) {
                    int idx = jB + lane;
                    int s = (idx < eB) ? g_csr[idx] : 0;
                    vB = g_nf[s];
                    mB = eB - jB; if (mB > 32) mB = 32;
                }
                if (mA) accum_chunk(vA, mA, accA0, accA1, wl0, wr0, bb0, wl1, wr1, bb1);
                if (mB) accum_chunk(vB, mB, accB0, accB1, wl0, wr0, bb0, wl1, wr1, bb1);
                jA += 32;
                jB += 32;
            }
            float invA = 1.0f / fmaxf(degA, 1.0f);
            float invB = 1.0f / fmaxf(degB, 1.0f);
            sA[lane * SASTR + nlA]        = accA0 * invA;
            sA[(lane + 32) * SASTR + nlA] = accA1 * invA;
            sA[lane * SASTR + nlB]        = accB0 * invB;
            sA[(lane + 32) * SASTR + nlB] = accB1 * invB;
        }
    }
    __syncthreads();

    // ---- Phase B: GEMM, 2 K-chunks, 4x4 micro-tile, packed f32x2 FMA ----
    ull acc2[4][2] = {};
#pragma unroll
    for (int ch = 0; ch < 2; ch++) {
#pragma unroll
        for (int k = 0; k < 64; k++) {
            float4 a = *(const float4*)&sA[k * SASTR + ty * 4];
            ulonglong2 b = *(const ulonglong2*)&sB[k * SASTR + tx * 4];
            ull a0 = pk2(a.x, a.x), a1 = pk2(a.y, a.y);
            ull a2 = pk2(a.z, a.z), a3 = pk2(a.w, a.w);
            acc2[0][0] = fma2(a0, b.x, acc2[0][0]); acc2[0][1] = fma2(a0, b.y, acc2[0][1]);
            acc2[1][0] = fma2(a1, b.x, acc2[1][0]); acc2[1][1] = fma2(a1, b.y, acc2[1][1]);
            acc2[2][0] = fma2(a2, b.x, acc2[2][0]); acc2[2][1] = fma2(a2, b.y, acc2[2][1]);
            acc2[3][0] = fma2(a3, b.x, acc2[3][0]); acc2[3][1] = fma2(a3, b.y, acc2[3][1]);
        }
        __syncthreads();
        if (ch == 0) {
            // refill sA with on-the-fly h1, sB with W2r
#pragma unroll
            for (int i = 0; i < 16; i++) {
                int idx = t + i * 256;
                int f = idx & 63, n = idx >> 6;
                float2 nf = sNF[n];
                float v = fmaxf(fmaf(nf.x, W1l[f], fmaf(nf.y, W1r[f], b1[f])), 0.0f);
                if (n0 + n >= N_NODES) v = 0.0f;
                sA[f * SASTR + n] = v;
            }
#pragma unroll
            for (int i = 0; i < 16; i++) {
                int idx = t + i * 256;
                int f = idx & 63, k = idx >> 6;
                sB[k * SASTR + f] = W2r[k * HID + f];
            }
            __syncthreads();
        }
    }

    // ---- Phase C: bias + relu -> stage h2 into sA [node][feat], then pool ----
#pragma unroll
    for (int i = 0; i < 4; i++) {
        float2 p0 = unpk2(acc2[i][0]);
        float2 p1 = unpk2(acc2[i][1]);
        int nrow = (ty * 4 + i) * SASTR + tx * 4;
        sA[nrow + 0] = fmaxf(p0.x + b2[tx * 4 + 0], 0.0f);
        sA[nrow + 1] = fmaxf(p0.y + b2[tx * 4 + 1], 0.0f);
        sA[nrow + 2] = fmaxf(p1.x + b2[tx * 4 + 2], 0.0f);
        sA[nrow + 3] = fmaxf(p1.y + b2[tx * 4 + 3], 0.0f);
    }
    __syncthreads();

    {
        int f = t & 63;
        int g = t >> 6;
        int cur = -2;
        float racc = 0.0f;
#pragma unroll
        for (int i = 0; i < 16; i++) {
            int n = g * 16 + i;
            int b = sBatch[n];
            if (b != cur) {
                if (cur >= 0) atomicAdd(&g_pool[cur * HID + f], racc);
                racc = 0.0f;
                cur = b;
            }
            if (b >= 0) racc += sA[n * SASTR + f];
        }
        if (cur >= 0) atomicAdd(&g_pool[cur * HID + f], racc);
    }
}

// ---- #4 classifier + restore-zeros for next replay ----
__global__ void final_kernel(const float* __restrict__ Wc,
                             const float* __restrict__ bc,
                             float* __restrict__ out) {
    int g = blockIdx.x;
    int lt = threadIdx.x;     // 32 threads

    if (lt < NCLS) {
        float inv = 1.0f / fmaxf(g_gcnt[g], 1.0f);
        float acc = bc[lt];
#pragma unroll
        for (int k = 0; k < HID; k++) {
            acc += g_pool[g * HID + k] * inv * Wc[k * NCLS + lt];
        }
        out[g * NCLS + lt] = acc;
    }
    __syncwarp();

#pragma unroll
    for (int k = lt; k < HID; k += 32) g_pool[g * HID + k] = 0.0f;
    if (lt == 0) g_gcnt[g] = 0.0f;

    int tid = g * 32 + lt;
    int stride = N_GRAPHS * 32;
    for (int j = tid; j < N_NODES; j += stride) { g_cursor[j] = 0; g_agg1[j] = 0.0f; }
}

extern "C" void kernel_launch(void* const* d_in, const int* in_sizes, int n_in,
                              void* d_out, int out_size) {
    const float* x    = (const float*)d_in[0];
    const int*   ei   = (const int*)d_in[1];
    const int*   bat  = (const int*)d_in[2];
    const float* W1l  = (const float*)d_in[3];
    const float* b1   = (const float*)d_in[4];
    const float* W1r  = (const float*)d_in[5];
    const float* W2l  = (const float*)d_in[6];
    const float* b2   = (const float*)d_in[7];
    const float* W2r  = (const float*)d_in[8];
    const float* Wc   = (const float*)d_in[9];
    const float* bc   = (const float*)d_in[10];
    float*       out  = (float*)d_out;

    (void)in_sizes; (void)n_in; (void)out_size;

    ell_kernel<<<(N_EDGES + 255) / 256, 256>>>(ei, bat, x);       // #1
    nf_kernel<<<(N_NODES + 255) / 256, 256>>>(x);                  // #2
    h2pool_gemm<<<(N_NODES + 63) / 64, 256>>>(bat, W2l, b2, W2r,   // #3
                                              W1l, b1, W1r);
    final_kernel<<<N_GRAPHS, 32>>>(Wc, bc, out);                   // #4
}